// round 11
// baseline (speedup 1.0000x reference)
#include <cuda_runtime.h>

#define NBLK 128
#define NTHR 384
#define B_ 2
#define M_ 768
#define N_ 512
#define MN_ (M_*N_)
#define AW (1.0f/768.0f)
#define BW (1.0f/512.0f)
#define EPSI 20.0f
#define RPB 12            // rows per block: 128*12 = 1536 = B*M
#define AS_STRIDE 100     // 96+4: multiple of 4 floats -> aligned broadcast LDS.128
#define AS_BUF (16*AS_STRIDE)
#define BS_BUF (16*64)

// dynamic smem layout (floats)
#define OFF_KS   0                       // 12*512 = 6144
#define OFF_AS   6144                    // 2*1600 = 3200
#define OFF_BS   (OFF_AS + 2*AS_BUF)     // 2*1024 = 2048
#define OFF_RED  (OFF_BS + 2*BS_BUF)     // 384
#define OFF_LOC  (OFF_RED + NTHR)        // 16
#define SMEM_FLOATS (OFF_LOC + 16)
#define SMEM_BYTES  (SMEM_FLOATS*4)

typedef unsigned long long ull;

// ---------------- device scratch ----------------
__device__ float g_P [B_*MN_];
__device__ float g_Km[B_*MN_];
__device__ float g_T [B_*MN_];
__device__ float g_rm[B_*M_];
__device__ float g_t1[B_*M_];
__device__ float g_t2[B_*N_];
__device__ float g_part[B_*N_*64];   // [batch][col][contributor] transposed partials
__device__ float g_tv[B_*N_];        // current t vector
__device__ float g_cp[128];
__device__ float g_acc[4];
__device__ unsigned g_bar[64];       // [0] batch0 counter, [32] batch1

__global__ void reset_kernel() { g_bar[0] = 0u; g_bar[32] = 0u; }

// ------- per-batch count barrier (R5): release-arrive, acquire-poll --------
__device__ __forceinline__ void gsync(unsigned &gen, unsigned* ctr) {
    ++gen;
    __syncthreads();
    if (threadIdx.x == 0) {
        asm volatile("red.release.gpu.global.add.u32 [%0], %1;"
                     :: "l"(ctr), "r"(1u) : "memory");
        unsigned target = gen * 64u;
        unsigned v;
        do {
            asm volatile("ld.acquire.gpu.global.b32 %0, [%1];"
                         : "=r"(v) : "l"(ctr) : "memory");
        } while (v < target);
    }
    __syncthreads();
}

// ---------------- packed f32x2 helpers ----------------
__device__ __forceinline__ void fma2(ull &d, ull a, ull b) {
    asm("fma.rn.f32x2 %0, %1, %2, %0;" : "+l"(d) : "l"(a), "l"(b));
}
__device__ __forceinline__ ull splat(float x) {
    ull r; asm("mov.b64 %0, {%1, %1};" : "=l"(r) : "f"(x)); return r;
}

// ---------------- GEMM tile 96x64 (128 tiles), 384 thr, micro 8x2 ----------
template<int MODE>
__device__ void gemm_tile(int tile, const float* __restrict__ D1,
                          const float* __restrict__ D2,
                          float* As, float* Bs, float* red) {
    const int Kd  = (MODE == 0) ? N_ : M_;
    const int lda = (MODE == 0) ? N_ : M_;
    int b = tile >> 6;
    int r = tile & 63;
    int row0 = (r >> 3) * 96;
    int col0 = (r & 7) * 64;
    const float* A  = (MODE == 0) ? (g_P + (size_t)b*MN_) : (D1 + (size_t)b*M_*M_);
    const float* Bm = (MODE == 0) ? (D2 + (size_t)b*(size_t)N_*N_)
                    : (MODE == 1) ? (g_T + (size_t)b*MN_)
                                  : (g_P + (size_t)b*MN_);
    int tid = threadIdx.x;
    int wid8 = (tid >> 5) * 8;
    int lane = tid & 31;
    int colp = lane * 2;

    int lr = tid >> 2;
    int lk = (tid & 3) * 4;
    const float* ApL = A + (size_t)(row0 + lr)*lda + lk;
    int brow = tid >> 4, bq = tid & 15;
    const float* BpL = Bm + (size_t)brow*N_ + col0 + bq*4;

    ull acc[4][2];
    #pragma unroll
    for (int i = 0; i < 4; i++) { acc[i][0] = 0ull; acc[i][1] = 0ull; }

    float4 pa = *(const float4*)(ApL);
    float4 pb;
    if (tid < 256) pb = *(const float4*)(BpL);

    int buf = 0;
    for (int k0 = 0; k0 < Kd; k0 += 16) {
        float* Asb = As + buf*AS_BUF;
        float* Bsb = Bs + buf*BS_BUF;
        Asb[(lk+0)*AS_STRIDE + lr] = pa.x;
        Asb[(lk+1)*AS_STRIDE + lr] = pa.y;
        Asb[(lk+2)*AS_STRIDE + lr] = pa.z;
        Asb[(lk+3)*AS_STRIDE + lr] = pa.w;
        if (tid < 256) *(float4*)&Bsb[brow*64 + bq*4] = pb;
        if (k0 + 16 < Kd) {
            pa = *(const float4*)(ApL + k0 + 16);
            if (tid < 256) pb = *(const float4*)(BpL + (size_t)(k0+16)*N_);
        }
        __syncthreads();
        #pragma unroll
        for (int k = 0; k < 16; k++) {
            const float* ap = Asb + k*AS_STRIDE + wid8;
            ulonglong2 ua0 = *(const ulonglong2*)(ap);
            ulonglong2 ua1 = *(const ulonglong2*)(ap + 4);
            float2 bv = *(const float2*)&Bsb[k*64 + colp];
            ull b0 = splat(bv.x), b1 = splat(bv.y);
            fma2(acc[0][0], ua0.x, b0); fma2(acc[0][1], ua0.x, b1);
            fma2(acc[1][0], ua0.y, b0); fma2(acc[1][1], ua0.y, b1);
            fma2(acc[2][0], ua1.x, b0); fma2(acc[2][1], ua1.x, b1);
            fma2(acc[3][0], ua1.y, b0); fma2(acc[3][1], ua1.y, b1);
        }
        buf ^= 1;
    }

    float cS[8][2];
    #pragma unroll
    for (int p = 0; p < 4; p++)
        #pragma unroll
        for (int j = 0; j < 2; j++) {
            union { ull u; float f[2]; } cv; cv.u = acc[p][j];
            cS[2*p][j]   = cv.f[0];
            cS[2*p+1][j] = cv.f[1];
        }

    if (MODE == 0) {
        float* Cb = g_T + (size_t)b*MN_;
        #pragma unroll
        for (int rr = 0; rr < 8; rr++) {
            int row = row0 + wid8 + rr;
            float2 v = make_float2(cS[rr][0], cS[rr][1]);
            *(float2*)(Cb + (size_t)row*N_ + col0 + colp) = v;
        }
    } else if (MODE == 1) {
        float* Cb = g_Km + (size_t)b*MN_;
        const float* t1b = g_t1 + b*M_;
        const float* t2b = g_t2 + b*N_;
        float t20 = t2b[col0+colp], t21 = t2b[col0+colp+1];
        #pragma unroll
        for (int rr = 0; rr < 8; rr++) {
            int row = row0 + wid8 + rr;
            float t1v = t1b[row];
            float2 v;
            v.x = __expf((2.0f*cS[rr][0] - t1v - t20) * EPSI);
            v.y = __expf((2.0f*cS[rr][1] - t1v - t21) * EPSI);
            *(float2*)(Cb + (size_t)row*N_ + col0 + colp) = v;
        }
    } else {
        const float* Tb = g_T + (size_t)b*MN_;
        float local = 0.f;
        #pragma unroll
        for (int rr = 0; rr < 8; rr++) {
            int row = row0 + wid8 + rr;
            float2 tv = *(const float2*)(Tb + (size_t)row*N_ + col0 + colp);
            local += cS[rr][0]*tv.x + cS[rr][1]*tv.y;
        }
        red[tid] = local;
        __syncthreads();
        if (tid < 128) red[tid] += red[tid + 128] + red[tid + 256];
        __syncthreads();
        for (int st = 64; st; st >>= 1) {
            if (tid < st) red[tid] += red[tid + st];
            __syncthreads();
        }
        if (!tid) g_cp[tile] = red[0];
    }
}

// ---------------- t1 = (D1.^2) @ rm  (warp per row, 12 warps) --------------
__device__ void sqmv_t1(const float* __restrict__ D1, int bid, int wid, int lane) {
    int fi = bid*RPB + wid;
    int b2 = fi >= M_;
    int i  = fi - b2*M_;
    const float4* row = (const float4*)(D1 + ((size_t)b2*M_ + i)*M_);
    const float4* rmb = (const float4*)(g_rm + b2*M_);
    float s = 0.f;
    for (int q = lane; q < 192; q += 32) {
        float4 v  = row[q];
        float4 r4 = rmb[q];
        s += v.x*v.x*r4.x + v.y*v.y*r4.y + v.z*v.z*r4.z + v.w*v.w*r4.w;
    }
    #pragma unroll
    for (int o = 16; o; o >>= 1) s += __shfl_xor_sync(0xffffffffu, s, o);
    if (!lane) g_t1[fi] = s;
}

// ---------------- persistent mega-kernel ----------------
__global__ void __launch_bounds__(NTHR)
gw_kernel(const float* __restrict__ D1, const float* __restrict__ D2,
          float* __restrict__ out, int out_size) {
    extern __shared__ float dyn[];
    float* sKs  = dyn + OFF_KS;
    float* As   = dyn + OFF_AS;
    float* Bs   = dyn + OFF_BS;
    float* sRed = dyn + OFF_RED;
    float* sLoc = dyn + OFF_LOC;

    int bid = blockIdx.x, tid = threadIdx.x;
    int wid = tid >> 5, lane = tid & 31;
    unsigned gen = 0;
    int bb = bid >> 6;                          // batch (64 blocks each)
    int lid6 = bid & 63;
    unsigned* ctr = &g_bar[bb*32];
    size_t rowbase = (size_t)bid * (RPB*N_);

    // ---------- Phase I: init P, rm, t2 ----------
    for (int idx = tid; idx < RPB*N_; idx += NTHR) g_P[rowbase + idx] = AW*BW;
    if (tid < RPB) g_rm[bid*RPB + tid] = AW;
    if (wid < 8) {
        int gw2 = bid*8 + wid;
        int b2 = gw2 >> 9, j = gw2 & 511;
        const float4* row = (const float4*)(D2 + ((size_t)b2*N_ + j)*N_);
        float s = 0.f;
        for (int q = lane; q < 128; q += 32) {
            float4 v = row[q];
            s += v.x*v.x + v.y*v.y + v.z*v.z + v.w*v.w;
        }
        #pragma unroll
        for (int o = 16; o; o >>= 1) s += __shfl_xor_sync(0xffffffffu, s, o);
        if (!lane) g_t2[gw2] = BW * s;
    }
    gsync(gen, ctr);

    for (int outer = 0; outer < 10; outer++) {
        // Phase A: T = P@D2 (1 tile/block) + t1 sqmv
        gemm_tile<0>(bid, D1, D2, As, Bs, sRed);
        sqmv_t1(D1, bid, wid, lane);
        gsync(gen, ctr);

        // Phase B: Km = exp(...)
        gemm_tile<1>(bid, D1, D2, As, Bs, sRed);
        gsync(gen, ctr);

        // Sinkhorn: 20 iterations, store/owner-reduce exchange (2 barriers/iter)
        for (int it = 0; it < 20; it++) {
            if (it == 0) {
                const float4* src = (const float4*)(g_Km + rowbase);
                float4* dst = (float4*)sKs;
                for (int idx = tid; idx < RPB*N_/4; idx += NTHR) dst[idx] = src[idx];
                __syncthreads();
            }
            // u-dot: warp wid handles row wid; t read via __ldcg (L2)
            {
                float s = 0.f;
                if (it == 0) {
                    for (int q = lane; q < 128; q += 32) {
                        float4 v = *(const float4*)&sKs[wid*N_ + q*4];
                        s += v.x + v.y + v.z + v.w;
                    }
                } else {
                    for (int q = lane; q < 128; q += 32) {
                        float4 v  = *(const float4*)&sKs[wid*N_ + q*4];
                        float4 t4 = __ldcg((const float4*)&g_tv[bb*N_ + q*4]);
                        s += v.x*t4.x + v.y*t4.y + v.z*t4.z + v.w*t4.w;
                    }
                }
                #pragma unroll
                for (int o = 16; o; o >>= 1) s += __shfl_xor_sync(0xffffffffu, s, o);
                if (!lane) sLoc[wid] = __fdividef(AW, s);
            }
            __syncthreads();
            // Phase U: column partials -> transposed plain stores (no atomics)
            {
                float a0 = 0.f;
                #pragma unroll
                for (int rr = 0; rr < RPB; rr++)
                    a0 += sKs[rr*N_ + tid] * sLoc[rr];
                g_part[((size_t)bb*N_ + tid)*64 + lid6] = a0;
                if (tid < 128) {
                    float a1 = 0.f;
                    #pragma unroll
                    for (int rr = 0; rr < RPB; rr++)
                        a1 += sKs[rr*N_ + tid + 384] * sLoc[rr];
                    g_part[((size_t)bb*N_ + tid + 384)*64 + lid6] = a1;
                }
            }
            gsync(gen, ctr);
            // Phase V: warp-per-column owner reduce (warps 0..7), write t
            if (wid < 8) {
                int col = lid6*8 + wid;
                const float* pp = g_part + ((size_t)bb*N_ + col)*64;
                float s = __ldcg(pp + lane) + __ldcg(pp + 32 + lane);
                #pragma unroll
                for (int o = 16; o; o >>= 1) s += __shfl_xor_sync(0xffffffffu, s, o);
                if (!lane) g_tv[bb*N_ + col] = __fdividef(BW, s);
            }
            gsync(gen, ctr);
        }

        // P update + row masses (warp per row), t via __ldcg
        {
            float s = 0.f;
            for (int q = lane; q < 128; q += 32) {
                float4 v  = *(const float4*)&sKs[wid*N_ + q*4];
                float4 t4 = __ldcg((const float4*)&g_tv[bb*N_ + q*4]);
                s += v.x*t4.x + v.y*t4.y + v.z*t4.z + v.w*t4.w;
            }
            #pragma unroll
            for (int o = 16; o; o >>= 1) s += __shfl_xor_sync(0xffffffffu, s, o);
            if (!lane) g_rm[bid*RPB + wid] = sLoc[wid] * s;
        }
        for (int c = tid; c < RPB*N_; c += NTHR) {
            int rr = c >> 9, j = c & 511;
            g_P[rowbase + c] = sLoc[rr] * sKs[c] * __ldcg(&g_tv[bb*N_ + j]);
        }
        gsync(gen, ctr);
    }

    // ---------- Final cost ----------
    gemm_tile<0>(bid, D1, D2, As, Bs, sRed);
    sqmv_t1(D1, bid, wid, lane);
    gsync(gen, ctr);

    gemm_tile<2>(bid, D1, D2, As, Bs, sRed);
    __syncthreads();
    if (lid6 == 0) {                       // blocks 0, 64: rm . t1
        float s = 0.f;
        for (int i = tid; i < M_; i += NTHR) s += g_rm[bb*M_ + i] * g_t1[bb*M_ + i];
        sRed[tid] = s;
        __syncthreads();
        if (tid < 128) sRed[tid] += sRed[tid + 128] + sRed[tid + 256];
        __syncthreads();
        for (int st = 64; st; st >>= 1) {
            if (tid < st) sRed[tid] += sRed[tid + st];
            __syncthreads();
        }
        if (!tid) g_acc[bb] = sRed[0];
    } else if (lid6 == 1) {                // blocks 1, 65: BW * sum t2
        float s = 0.f;
        for (int j = tid; j < N_; j += NTHR) s += g_t2[bb*N_ + j];
        sRed[tid] = s;
        __syncthreads();
        if (tid < 128) sRed[tid] += sRed[tid + 128] + sRed[tid + 256];
        __syncthreads();
        for (int st = 64; st; st >>= 1) {
            if (tid < st) sRed[tid] += sRed[tid + st];
            __syncthreads();
        }
        if (!tid) g_acc[2 + bb] = BW * sRed[0];
    }
    gsync(gen, ctr);

    // outputs
    if (lid6 == 0 && tid == 0) {
        float cr = 0.f;
        for (int t = 0; t < 64; t++) cr += g_cp[bb*64 + t];
        out[bb] = g_acc[bb] + g_acc[2 + bb] - 2.0f*cr;
    }
    if (out_size > 2) {
        const float2* src = (const float2*)(g_P + rowbase);
        float2* dst = (float2*)(out + 2 + rowbase);
        for (int idx = tid; idx < RPB*N_/2; idx += NTHR) dst[idx] = src[idx];
    }
}

// ---------------- host driver ----------------
extern "C" void kernel_launch(void* const* d_in, const int* in_sizes, int n_in,
                              void* d_out, int out_size) {
    const float* D1 = (const float*)d_in[0];
    const float* D2 = (const float*)d_in[1];
    if (n_in >= 2 && in_sizes[0] == B_*N_*N_ && in_sizes[1] == B_*M_*M_) {
        const float* tmp = D1; D1 = D2; D2 = tmp;
    }
    float* out = (float*)d_out;

    static int configured = 0;
    if (!configured) {
        cudaFuncSetAttribute(gw_kernel,
                             cudaFuncAttributeMaxDynamicSharedMemorySize,
                             SMEM_BYTES);
        configured = 1;
    }
    reset_kernel<<<1, 1>>>();
    gw_kernel<<<NBLK, NTHR, SMEM_BYTES>>>(D1, D2, out, out_size);
}

// round 13
// speedup vs baseline: 1.4873x; 1.4873x over previous
#include <cuda_runtime.h>

#define NBLK 128
#define NTHR 384
#define B_ 2
#define M_ 768
#define N_ 512
#define MN_ (M_*N_)
#define AW (1.0f/768.0f)
#define BW (1.0f/512.0f)
#define EPSI 20.0f
#define RPB 12            // rows per block: 128*12 = 1536 = B*M
#define KC 32             // GEMM k-chunk
#define AS_STRIDE 100     // 96+4: multiple of 4 floats -> aligned broadcast LDS.128
#define AS_BUF (KC*AS_STRIDE)
#define BS_BUF (KC*64)

// dynamic smem layout (floats)
#define OFF_KS   0                       // 12*512 = 6144
#define OFF_AS   6144                    // 2*3200 = 6400
#define OFF_BS   (OFF_AS + 2*AS_BUF)     // 2*2048 = 4096
#define OFF_TS   (OFF_BS + 2*BS_BUF)     // 512
#define OFF_RED  (OFF_TS + 512)          // 384
#define OFF_LOC  (OFF_RED + NTHR)        // 16
#define SMEM_FLOATS (OFF_LOC + 16)
#define SMEM_BYTES  (SMEM_FLOATS*4)

typedef unsigned long long ull;

// ---------------- device scratch ----------------
__device__ float g_P [B_*MN_];
__device__ float g_Km[B_*MN_];
__device__ float g_T [B_*MN_];
__device__ float g_rm[B_*M_];
__device__ float g_t1[B_*M_];
__device__ float g_t2[B_*N_];
__device__ float g_csum[3][B_*N_];   // triple-buffered atomic column sums
__device__ float g_cp[128];
__device__ float g_acc[4];
__device__ unsigned g_bar[64];       // [0] batch0 counter, [32] batch1

__global__ void reset_kernel() { g_bar[0] = 0u; g_bar[32] = 0u; }

// ------- per-batch count barrier (R5/R10): release-arrive, acquire-poll ----
__device__ __forceinline__ void gsync(unsigned &gen, unsigned* ctr) {
    ++gen;
    __syncthreads();
    if (threadIdx.x == 0) {
        asm volatile("red.release.gpu.global.add.u32 [%0], %1;"
                     :: "l"(ctr), "r"(1u) : "memory");
        unsigned target = gen * 64u;
        unsigned v;
        do {
            asm volatile("ld.acquire.gpu.global.b32 %0, [%1];"
                         : "=r"(v) : "l"(ctr) : "memory");
        } while (v < target);
    }
    __syncthreads();
}

// ---------------- packed f32x2 helpers ----------------
__device__ __forceinline__ void fma2(ull &d, ull a, ull b) {
    asm("fma.rn.f32x2 %0, %1, %2, %0;" : "+l"(d) : "l"(a), "l"(b));
}
__device__ __forceinline__ ull splat(float x) {
    ull r; asm("mov.b64 %0, {%1, %1};" : "=l"(r) : "f"(x)); return r;
}

// ---------------- GEMM tile 96x64 (128 tiles), 384 thr, micro 8x2, KC=32 ---
// Warp = row-group of 8 rows (A reads broadcast LDS.128), lane = column pair
// (B reads conflict-free LDS.64). 32-deep k-chunks: half the syncs of KC=16.
template<int MODE>
__device__ void gemm_tile(int tile, const float* __restrict__ D1,
                          const float* __restrict__ D2,
                          float* As, float* Bs, float* red) {
    const int Kd  = (MODE == 0) ? N_ : M_;
    const int lda = (MODE == 0) ? N_ : M_;
    int b = tile >> 6;
    int r = tile & 63;
    int row0 = (r >> 3) * 96;
    int col0 = (r & 7) * 64;
    const float* A  = (MODE == 0) ? (g_P + (size_t)b*MN_) : (D1 + (size_t)b*M_*M_);
    const float* Bm = (MODE == 0) ? (D2 + (size_t)b*(size_t)N_*N_)
                    : (MODE == 1) ? (g_T + (size_t)b*MN_)
                                  : (g_P + (size_t)b*MN_);
    int tid = threadIdx.x;
    int wid8 = (tid >> 5) * 8;
    int lane = tid & 31;
    int colp = lane * 2;

    // A loader: 96 rows x 32 k = 768 float4; each thread 2 (f=tid, tid+384)
    int lr0 = tid >> 3;                 // 0..47
    int lk0 = (tid & 7) * 4;            // 0,4,..,28
    const float* ApL0 = A + (size_t)(row0 + lr0)*lda + lk0;
    const float* ApL1 = ApL0 + (size_t)48*lda;      // rows 48..95
    // B loader: 32 k x 64 cols = 512 float4; f=tid (all), f=tid+384 (tid<128)
    int brow0 = tid >> 4, bq0 = tid & 15;
    const float* BpL0 = Bm + (size_t)brow0*N_ + col0 + bq0*4;
    const float* BpL1 = BpL0 + (size_t)24*N_;       // k-rows 24..31

    ull acc[4][2];
    #pragma unroll
    for (int i = 0; i < 4; i++) { acc[i][0] = 0ull; acc[i][1] = 0ull; }

    float4 pa0 = *(const float4*)(ApL0);
    float4 pa1 = *(const float4*)(ApL1);
    float4 pb0, pb1;
    pb0 = *(const float4*)(BpL0);
    if (tid < 128) pb1 = *(const float4*)(BpL1);

    int buf = 0;
    for (int k0 = 0; k0 < Kd; k0 += KC) {
        float* Asb = As + buf*AS_BUF;
        float* Bsb = Bs + buf*BS_BUF;
        Asb[(lk0+0)*AS_STRIDE + lr0] = pa0.x;
        Asb[(lk0+1)*AS_STRIDE + lr0] = pa0.y;
        Asb[(lk0+2)*AS_STRIDE + lr0] = pa0.z;
        Asb[(lk0+3)*AS_STRIDE + lr0] = pa0.w;
        Asb[(lk0+0)*AS_STRIDE + lr0 + 48] = pa1.x;
        Asb[(lk0+1)*AS_STRIDE + lr0 + 48] = pa1.y;
        Asb[(lk0+2)*AS_STRIDE + lr0 + 48] = pa1.z;
        Asb[(lk0+3)*AS_STRIDE + lr0 + 48] = pa1.w;
        *(float4*)&Bsb[brow0*64 + bq0*4] = pb0;
        if (tid < 128) *(float4*)&Bsb[(brow0+24)*64 + bq0*4] = pb1;
        if (k0 + KC < Kd) {
            pa0 = *(const float4*)(ApL0 + k0 + KC);
            pa1 = *(const float4*)(ApL1 + k0 + KC);
            pb0 = *(const float4*)(BpL0 + (size_t)(k0+KC)*N_);
            if (tid < 128) pb1 = *(const float4*)(BpL1 + (size_t)(k0+KC)*N_);
        }
        __syncthreads();
        #pragma unroll
        for (int k = 0; k < KC; k++) {
            const float* ap = Asb + k*AS_STRIDE + wid8;
            ulonglong2 ua0 = *(const ulonglong2*)(ap);      // rows 0-3 (broadcast)
            ulonglong2 ua1 = *(const ulonglong2*)(ap + 4);  // rows 4-7 (broadcast)
            float2 bv = *(const float2*)&Bsb[k*64 + colp];
            ull b0 = splat(bv.x), b1 = splat(bv.y);
            fma2(acc[0][0], ua0.x, b0); fma2(acc[0][1], ua0.x, b1);
            fma2(acc[1][0], ua0.y, b0); fma2(acc[1][1], ua0.y, b1);
            fma2(acc[2][0], ua1.x, b0); fma2(acc[2][1], ua1.x, b1);
            fma2(acc[3][0], ua1.y, b0); fma2(acc[3][1], ua1.y, b1);
        }
        buf ^= 1;
    }

    float cS[8][2];
    #pragma unroll
    for (int p = 0; p < 4; p++)
        #pragma unroll
        for (int j = 0; j < 2; j++) {
            union { ull u; float f[2]; } cv; cv.u = acc[p][j];
            cS[2*p][j]   = cv.f[0];
            cS[2*p+1][j] = cv.f[1];
        }

    if (MODE == 0) {
        float* Cb = g_T + (size_t)b*MN_;
        #pragma unroll
        for (int rr = 0; rr < 8; rr++) {
            int row = row0 + wid8 + rr;
            float2 v = make_float2(cS[rr][0], cS[rr][1]);
            *(float2*)(Cb + (size_t)row*N_ + col0 + colp) = v;
        }
    } else if (MODE == 1) {
        float* Cb = g_Km + (size_t)b*MN_;
        const float* t1b = g_t1 + b*M_;
        const float* t2b = g_t2 + b*N_;
        float t20 = t2b[col0+colp], t21 = t2b[col0+colp+1];
        #pragma unroll
        for (int rr = 0; rr < 8; rr++) {
            int row = row0 + wid8 + rr;
            float t1v = t1b[row];
            float2 v;
            v.x = __expf((2.0f*cS[rr][0] - t1v - t20) * EPSI);
            v.y = __expf((2.0f*cS[rr][1] - t1v - t21) * EPSI);
            *(float2*)(Cb + (size_t)row*N_ + col0 + colp) = v;
        }
    } else {
        const float* Tb = g_T + (size_t)b*MN_;
        float local = 0.f;
        #pragma unroll
        for (int rr = 0; rr < 8; rr++) {
            int row = row0 + wid8 + rr;
            float2 tv = *(const float2*)(Tb + (size_t)row*N_ + col0 + colp);
            local += cS[rr][0]*tv.x + cS[rr][1]*tv.y;
        }
        red[tid] = local;
        __syncthreads();
        if (tid < 128) red[tid] += red[tid + 128] + red[tid + 256];
        __syncthreads();
        for (int st = 64; st; st >>= 1) {
            if (tid < st) red[tid] += red[tid + st];
            __syncthreads();
        }
        if (!tid) g_cp[tile] = red[0];
    }
}

// ---------------- t1 = (D1.^2) @ rm  (warp per row, 12 warps) --------------
__device__ void sqmv_t1(const float* __restrict__ D1, int bid, int wid, int lane) {
    int fi = bid*RPB + wid;
    int b2 = fi >= M_;
    int i  = fi - b2*M_;
    const float4* row = (const float4*)(D1 + ((size_t)b2*M_ + i)*M_);
    const float4* rmb = (const float4*)(g_rm + b2*M_);
    float s = 0.f;
    for (int q = lane; q < 192; q += 32) {
        float4 v  = row[q];
        float4 r4 = rmb[q];
        s += v.x*v.x*r4.x + v.y*v.y*r4.y + v.z*v.z*r4.z + v.w*v.w*r4.w;
    }
    #pragma unroll
    for (int o = 16; o; o >>= 1) s += __shfl_xor_sync(0xffffffffu, s, o);
    if (!lane) g_t1[fi] = s;
}

// ---------------- persistent mega-kernel ----------------
__global__ void __launch_bounds__(NTHR)
gw_kernel(const float* __restrict__ D1, const float* __restrict__ D2,
          float* __restrict__ out, int out_size) {
    extern __shared__ float dyn[];
    float* sKs  = dyn + OFF_KS;
    float* As   = dyn + OFF_AS;
    float* Bs   = dyn + OFF_BS;
    float* tS   = dyn + OFF_TS;
    float* sRed = dyn + OFF_RED;
    float* sLoc = dyn + OFF_LOC;

    int bid = blockIdx.x, tid = threadIdx.x;
    int wid = tid >> 5, lane = tid & 31;
    unsigned gen = 0;
    int bb = bid >> 6;                          // batch (64 blocks each)
    int lid6 = bid & 63;
    unsigned* ctr = &g_bar[bb*32];
    size_t rowbase = (size_t)bid * (RPB*N_);

    // ---------- Phase I: init P, rm, t2, csum[0] ----------
    for (int idx = tid; idx < RPB*N_; idx += NTHR) g_P[rowbase + idx] = AW*BW;
    if (tid < RPB) g_rm[bid*RPB + tid] = AW;
    if (wid < 8) {
        int gw2 = bid*8 + wid;
        int b2 = gw2 >> 9, j = gw2 & 511;
        const float4* row = (const float4*)(D2 + ((size_t)b2*N_ + j)*N_);
        float s = 0.f;
        for (int q = lane; q < 128; q += 32) {
            float4 v = row[q];
            s += v.x*v.x + v.y*v.y + v.z*v.z + v.w*v.w;
        }
        #pragma unroll
        for (int o = 16; o; o >>= 1) s += __shfl_xor_sync(0xffffffffu, s, o);
        if (!lane) g_t2[gw2] = BW * s;
    }
    if (lid6 == 0)
        for (int idx = tid; idx < N_; idx += NTHR) g_csum[0][bb*N_ + idx] = 0.f;
    gsync(gen, ctr);

    int git = 0;
    for (int outer = 0; outer < 10; outer++) {
        // Phase A: T = P@D2 (1 tile/block) + t1 sqmv
        gemm_tile<0>(bid, D1, D2, As, Bs, sRed);
        sqmv_t1(D1, bid, wid, lane);
        gsync(gen, ctr);

        // Phase B: Km = exp(...)
        gemm_tile<1>(bid, D1, D2, As, Bs, sRed);
        gsync(gen, ctr);

        // Sinkhorn: 20 iterations, 1 barrier each (R10 machinery, unchanged)
        for (int it = 0; it < 20; it++, git++) {
            if (it == 0) {
                const float4* src = (const float4*)(g_Km + rowbase);
                float4* dst = (float4*)sKs;
                for (int idx = tid; idx < RPB*N_/4; idx += NTHR) dst[idx] = src[idx];
                __syncthreads();
            }
            // u-dot: warp wid handles row wid
            {
                float s = 0.f;
                if (it == 0) {
                    for (int q = lane; q < 128; q += 32) {
                        float4 v = *(const float4*)&sKs[wid*N_ + q*4];
                        s += v.x + v.y + v.z + v.w;
                    }
                } else {
                    for (int q = lane; q < 128; q += 32) {
                        float4 v  = *(const float4*)&sKs[wid*N_ + q*4];
                        float4 t4 = *(const float4*)&tS[q*4];
                        s += v.x*t4.x + v.y*t4.y + v.z*t4.z + v.w*t4.w;
                    }
                }
                #pragma unroll
                for (int o = 16; o; o >>= 1) s += __shfl_xor_sync(0xffffffffu, s, o);
                if (!lane) sLoc[wid] = __fdividef(AW, s);
            }
            __syncthreads();
            // column partials -> scalar atomic accumulate; zero next buffer
            {
                int p = git % 3;
                float a0 = 0.f;
                #pragma unroll
                for (int rr = 0; rr < RPB; rr++)
                    a0 += sKs[rr*N_ + tid] * sLoc[rr];
                atomicAdd(&g_csum[p][bb*N_ + tid], a0);
                if (tid < 128) {
                    float a1 = 0.f;
                    #pragma unroll
                    for (int rr = 0; rr < RPB; rr++)
                        a1 += sKs[rr*N_ + tid + 384] * sLoc[rr];
                    atomicAdd(&g_csum[p][bb*N_ + tid + 384], a1);
                }
                int pn = (p + 1 == 3) ? 0 : p + 1;
                if (tid < 8) g_csum[pn][bb*N_ + lid6*8 + tid] = 0.f;
            }
            gsync(gen, ctr);
            // t recompute (redundant per block, into SMEM)
            {
                int p = git % 3;
                tS[tid] = __fdividef(BW, g_csum[p][bb*N_ + tid]);
                if (tid < 128)
                    tS[tid + 384] = __fdividef(BW, g_csum[p][bb*N_ + tid + 384]);
            }
            __syncthreads();
        }

        // P update + row masses (warp per row)
        {
            float s = 0.f;
            for (int q = lane; q < 128; q += 32) {
                float4 v  = *(const float4*)&sKs[wid*N_ + q*4];
                float4 t4 = *(const float4*)&tS[q*4];
                s += v.x*t4.x + v.y*t4.y + v.z*t4.z + v.w*t4.w;
            }
            #pragma unroll
            for (int o = 16; o; o >>= 1) s += __shfl_xor_sync(0xffffffffu, s, o);
            if (!lane) g_rm[bid*RPB + wid] = sLoc[wid] * s;
        }
        for (int c = tid; c < RPB*N_; c += NTHR) {
            int rr = c >> 9, j = c & 511;
            g_P[rowbase + c] = sLoc[rr] * sKs[c] * tS[j];
        }
        gsync(gen, ctr);
    }

    // ---------- Final cost ----------
    gemm_tile<0>(bid, D1, D2, As, Bs, sRed);
    sqmv_t1(D1, bid, wid, lane);
    gsync(gen, ctr);

    gemm_tile<2>(bid, D1, D2, As, Bs, sRed);
    __syncthreads();
    if (lid6 == 0) {                       // blocks 0, 64: rm . t1
        float s = 0.f;
        for (int i = tid; i < M_; i += NTHR) s += g_rm[bb*M_ + i] * g_t1[bb*M_ + i];
        sRed[tid] = s;
        __syncthreads();
        if (tid < 128) sRed[tid] += sRed[tid + 128] + sRed[tid + 256];
        __syncthreads();
        for (int st = 64; st; st >>= 1) {
            if (tid < st) sRed[tid] += sRed[tid + st];
            __syncthreads();
        }
        if (!tid) g_acc[bb] = sRed[0];
    } else if (lid6 == 1) {                // blocks 1, 65: BW * sum t2
        float s = 0.f;
        for (int j = tid; j < N_; j += NTHR) s += g_t2[bb*N_ + j];
        sRed[tid] = s;
        __syncthreads();
        if (tid < 128) sRed[tid] += sRed[tid + 128] + sRed[tid + 256];
        __syncthreads();
        for (int st = 64; st; st >>= 1) {
            if (tid < st) sRed[tid] += sRed[tid + st];
            __syncthreads();
        }
        if (!tid) g_acc[2 + bb] = BW * sRed[0];
    }
    gsync(gen, ctr);

    // outputs
    if (lid6 == 0 && tid == 0) {
        float cr = 0.f;
        for (int t = 0; t < 64; t++) cr += g_cp[bb*64 + t];
        out[bb] = g_acc[bb] + g_acc[2 + bb] - 2.0f*cr;
    }
    if (out_size > 2) {
        const float2* src = (const float2*)(g_P + rowbase);
        float2* dst = (float2*)(out + 2 + rowbase);
        for (int idx = tid; idx < RPB*N_/2; idx += NTHR) dst[idx] = src[idx];
    }
}

// ---------------- host driver ----------------
extern "C" void kernel_launch(void* const* d_in, const int* in_sizes, int n_in,
                              void* d_out, int out_size) {
    const float* D1 = (const float*)d_in[0];
    const float* D2 = (const float*)d_in[1];
    if (n_in >= 2 && in_sizes[0] == B_*N_*N_ && in_sizes[1] == B_*M_*M_) {
        const float* tmp = D1; D1 = D2; D2 = tmp;
    }
    float* out = (float*)d_out;

    static int configured = 0;
    if (!configured) {
        cudaFuncSetAttribute(gw_kernel,
                             cudaFuncAttributeMaxDynamicSharedMemorySize,
                             SMEM_BYTES);
        configured = 1;
    }
    reset_kernel<<<1, 1>>>();
    gw_kernel<<<NBLK, NTHR, SMEM_BYTES>>>(D1, D2, out, out_size);
}

// round 15
// speedup vs baseline: 1.4980x; 1.0072x over previous
#include <cuda_runtime.h>

#define NBLK 128
#define NTHR 384
#define B_ 2
#define M_ 768
#define N_ 512
#define MN_ (M_*N_)
#define AW (1.0f/768.0f)
#define BW (1.0f/512.0f)
#define EPSI 20.0f
#define RPB 12            // rows per block: 128*12 = 1536 = B*M
#define AS_STRIDE 100     // 96+4: multiple of 4 floats -> aligned broadcast LDS.128
#define AS_BUF (16*AS_STRIDE)
#define BS_BUF (16*64)

// dynamic smem layout (floats)
#define OFF_KS   0                       // 12*512 = 6144
#define OFF_AS   6144                    // 2*1600 = 3200
#define OFF_BS   (OFF_AS + 2*AS_BUF)     // 2*1024 = 2048
#define OFF_TS   (OFF_BS + 2*BS_BUF)     // 512
#define OFF_RED  (OFF_TS + 512)          // 384
#define OFF_LOC  (OFF_RED + NTHR)        // 16
#define SMEM_FLOATS (OFF_LOC + 16)
#define SMEM_BYTES  (SMEM_FLOATS*4)

typedef unsigned long long ull;

// ---------------- device scratch ----------------
__device__ float g_P [B_*MN_];
__device__ float g_Km[B_*MN_];
__device__ float g_T [B_*MN_];
__device__ float g_rm[B_*M_];
__device__ float g_t1[B_*M_];
__device__ float g_t2[B_*N_];
__device__ float g_csum[3][B_*N_];   // triple-buffered atomic column sums
__device__ float g_cp[128];
__device__ float g_acc[4];
__device__ unsigned g_bar[64];       // [0] batch0 counter, [32] batch1

__global__ void reset_kernel() { g_bar[0] = 0u; g_bar[32] = 0u; }

// ------- per-batch count barrier (R5/R10): release-arrive, acquire-poll ----
__device__ __forceinline__ void gsync(unsigned &gen, unsigned* ctr) {
    ++gen;
    __syncthreads();
    if (threadIdx.x == 0) {
        asm volatile("red.release.gpu.global.add.u32 [%0], %1;"
                     :: "l"(ctr), "r"(1u) : "memory");
        unsigned target = gen * 64u;
        unsigned v;
        do {
            asm volatile("ld.acquire.gpu.global.b32 %0, [%1];"
                         : "=r"(v) : "l"(ctr) : "memory");
        } while (v < target);
    }
    __syncthreads();
}

// ---------------- packed f32x2 helpers ----------------
__device__ __forceinline__ void fma2(ull &d, ull a, ull b) {
    asm("fma.rn.f32x2 %0, %1, %2, %0;" : "+l"(d) : "l"(a), "l"(b));
}
__device__ __forceinline__ ull splat(float x) {
    ull r; asm("mov.b64 %0, {%1, %1};" : "=l"(r) : "f"(x)); return r;
}

// ---------------- GEMM tile 96x64 (128 tiles), 384 thr, micro 8x2 ----------
// Warp = row-group of 8 rows (A reads single-address broadcast LDS.128),
// lane = column pair (B reads conflict-free LDS.64).
template<int MODE>
__device__ void gemm_tile(int tile, const float* __restrict__ D1,
                          const float* __restrict__ D2,
                          float* As, float* Bs, float* red) {
    const int Kd  = (MODE == 0) ? N_ : M_;
    const int lda = (MODE == 0) ? N_ : M_;
    int b = tile >> 6;
    int r = tile & 63;
    int row0 = (r >> 3) * 96;
    int col0 = (r & 7) * 64;
    const float* A  = (MODE == 0) ? (g_P + (size_t)b*MN_) : (D1 + (size_t)b*M_*M_);
    const float* Bm = (MODE == 0) ? (D2 + (size_t)b*(size_t)N_*N_)
                    : (MODE == 1) ? (g_T + (size_t)b*MN_)
                                  : (g_P + (size_t)b*MN_);
    int tid = threadIdx.x;
    int wid8 = (tid >> 5) * 8;
    int lane = tid & 31;
    int colp = lane * 2;

    int lr = tid >> 2;
    int lk = (tid & 3) * 4;
    const float* ApL = A + (size_t)(row0 + lr)*lda + lk;
    int brow = tid >> 4, bq = tid & 15;
    const float* BpL = Bm + (size_t)brow*N_ + col0 + bq*4;

    ull acc[4][2];
    #pragma unroll
    for (int i = 0; i < 4; i++) { acc[i][0] = 0ull; acc[i][1] = 0ull; }

    float4 pa = *(const float4*)(ApL);
    float4 pb;
    if (tid < 256) pb = *(const float4*)(BpL);

    int buf = 0;
    for (int k0 = 0; k0 < Kd; k0 += 16) {
        float* Asb = As + buf*AS_BUF;
        float* Bsb = Bs + buf*BS_BUF;
        Asb[(lk+0)*AS_STRIDE + lr] = pa.x;
        Asb[(lk+1)*AS_STRIDE + lr] = pa.y;
        Asb[(lk+2)*AS_STRIDE + lr] = pa.z;
        Asb[(lk+3)*AS_STRIDE + lr] = pa.w;
        if (tid < 256) *(float4*)&Bsb[brow*64 + bq*4] = pb;
        if (k0 + 16 < Kd) {
            pa = *(const float4*)(ApL + k0 + 16);
            if (tid < 256) pb = *(const float4*)(BpL + (size_t)(k0+16)*N_);
        }
        __syncthreads();
        #pragma unroll
        for (int k = 0; k < 16; k++) {
            const float* ap = Asb + k*AS_STRIDE + wid8;
            ulonglong2 ua0 = *(const ulonglong2*)(ap);      // rows 0-3 (broadcast)
            ulonglong2 ua1 = *(const ulonglong2*)(ap + 4);  // rows 4-7 (broadcast)
            float2 bv = *(const float2*)&Bsb[k*64 + colp];
            ull b0 = splat(bv.x), b1 = splat(bv.y);
            fma2(acc[0][0], ua0.x, b0); fma2(acc[0][1], ua0.x, b1);
            fma2(acc[1][0], ua0.y, b0); fma2(acc[1][1], ua0.y, b1);
            fma2(acc[2][0], ua1.x, b0); fma2(acc[2][1], ua1.x, b1);
            fma2(acc[3][0], ua1.y, b0); fma2(acc[3][1], ua1.y, b1);
        }
        buf ^= 1;
    }

    float cS[8][2];
    #pragma unroll
    for (int p = 0; p < 4; p++)
        #pragma unroll
        for (int j = 0; j < 2; j++) {
            union { ull u; float f[2]; } cv; cv.u = acc[p][j];
            cS[2*p][j]   = cv.f[0];
            cS[2*p+1][j] = cv.f[1];
        }

    if (MODE == 0) {
        float* Cb = g_T + (size_t)b*MN_;
        #pragma unroll
        for (int rr = 0; rr < 8; rr++) {
            int row = row0 + wid8 + rr;
            float2 v = make_float2(cS[rr][0], cS[rr][1]);
            *(float2*)(Cb + (size_t)row*N_ + col0 + colp) = v;
        }
    } else if (MODE == 1) {
        float* Cb = g_Km + (size_t)b*MN_;
        const float* t1b = g_t1 + b*M_;
        const float* t2b = g_t2 + b*N_;
        float t20 = t2b[col0+colp], t21 = t2b[col0+colp+1];
        #pragma unroll
        for (int rr = 0; rr < 8; rr++) {
            int row = row0 + wid8 + rr;
            float t1v = t1b[row];
            float2 v;
            v.x = __expf((2.0f*cS[rr][0] - t1v - t20) * EPSI);
            v.y = __expf((2.0f*cS[rr][1] - t1v - t21) * EPSI);
            *(float2*)(Cb + (size_t)row*N_ + col0 + colp) = v;
        }
    } else {
        const float* Tb = g_T + (size_t)b*MN_;
        float local = 0.f;
        #pragma unroll
        for (int rr = 0; rr < 8; rr++) {
            int row = row0 + wid8 + rr;
            float2 tv = *(const float2*)(Tb + (size_t)row*N_ + col0 + colp);
            local += cS[rr][0]*tv.x + cS[rr][1]*tv.y;
        }
        red[tid] = local;
        __syncthreads();
        if (tid < 128) red[tid] += red[tid + 128] + red[tid + 256];
        __syncthreads();
        for (int st = 64; st; st >>= 1) {
            if (tid < st) red[tid] += red[tid + st];
            __syncthreads();
        }
        if (!tid) g_cp[tile] = red[0];
    }
}

// ---------------- t1 = (D1.^2) @ rm  (warp per row, 12 warps) --------------
__device__ void sqmv_t1(const float* __restrict__ D1, int bid, int wid, int lane) {
    int fi = bid*RPB + wid;
    int b2 = fi >= M_;
    int i  = fi - b2*M_;
    const float4* row = (const float4*)(D1 + ((size_t)b2*M_ + i)*M_);
    const float4* rmb = (const float4*)(g_rm + b2*M_);
    float s = 0.f;
    for (int q = lane; q < 192; q += 32) {
        float4 v  = row[q];
        float4 r4 = rmb[q];
        s += v.x*v.x*r4.x + v.y*v.y*r4.y + v.z*v.z*r4.z + v.w*v.w*r4.w;
    }
    #pragma unroll
    for (int o = 16; o; o >>= 1) s += __shfl_xor_sync(0xffffffffu, s, o);
    if (!lane) g_t1[fi] = s;
}

// ---------------- persistent mega-kernel ----------------
__global__ void __launch_bounds__(NTHR)
gw_kernel(const float* __restrict__ D1, const float* __restrict__ D2,
          float* __restrict__ out, int out_size) {
    extern __shared__ float dyn[];
    float* sKs  = dyn + OFF_KS;
    float* As   = dyn + OFF_AS;
    float* Bs   = dyn + OFF_BS;
    float* tS   = dyn + OFF_TS;
    float* sRed = dyn + OFF_RED;
    float* sLoc = dyn + OFF_LOC;

    int bid = blockIdx.x, tid = threadIdx.x;
    int wid = tid >> 5, lane = tid & 31;
    unsigned gen = 0;
    int bb = bid >> 6;                          // batch (64 blocks each)
    int lid6 = bid & 63;
    unsigned* ctr = &g_bar[bb*32];
    size_t rowbase = (size_t)bid * (RPB*N_);

    // ---------- Phase I: init P, rm, t2, csum[0] ----------
    for (int idx = tid; idx < RPB*N_; idx += NTHR) g_P[rowbase + idx] = AW*BW;
    if (tid < RPB) g_rm[bid*RPB + tid] = AW;
    if (wid < 8) {
        int gw2 = bid*8 + wid;
        int b2 = gw2 >> 9, j = gw2 & 511;
        const float4* row = (const float4*)(D2 + ((size_t)b2*N_ + j)*N_);
        float s = 0.f;
        for (int q = lane; q < 128; q += 32) {
            float4 v = row[q];
            s += v.x*v.x + v.y*v.y + v.z*v.z + v.w*v.w;
        }
        #pragma unroll
        for (int o = 16; o; o >>= 1) s += __shfl_xor_sync(0xffffffffu, s, o);
        if (!lane) g_t2[gw2] = BW * s;
    }
    if (lid6 == 0)
        for (int idx = tid; idx < N_; idx += NTHR) g_csum[0][bb*N_ + idx] = 0.f;
    gsync(gen, ctr);

    int git = 0;
    for (int outer = 0; outer < 10; outer++) {
        // Phase A: T = P@D2 (1 tile/block) + t1 sqmv
        gemm_tile<0>(bid, D1, D2, As, Bs, sRed);
        sqmv_t1(D1, bid, wid, lane);
        gsync(gen, ctr);

        // Phase B: Km = exp(...)
        gemm_tile<1>(bid, D1, D2, As, Bs, sRed);
        gsync(gen, ctr);

        // Sinkhorn: 20 iterations, 1 barrier each
        for (int it = 0; it < 20; it++, git++) {
            if (it == 0) {
                const float4* src = (const float4*)(g_Km + rowbase);
                float4* dst = (float4*)sKs;
                for (int idx = tid; idx < RPB*N_/4; idx += NTHR) dst[idx] = src[idx];
                __syncthreads();
            }
            // u-dot: warp wid handles row wid
            {
                float s = 0.f;
                if (it == 0) {
                    for (int q = lane; q < 128; q += 32) {
                        float4 v = *(const float4*)&sKs[wid*N_ + q*4];
                        s += v.x + v.y + v.z + v.w;
                    }
                } else {
                    for (int q = lane; q < 128; q += 32) {
                        float4 v  = *(const float4*)&sKs[wid*N_ + q*4];
                        float4 t4 = *(const float4*)&tS[q*4];
                        s += v.x*t4.x + v.y*t4.y + v.z*t4.z + v.w*t4.w;
                    }
                }
                #pragma unroll
                for (int o = 16; o; o >>= 1) s += __shfl_xor_sync(0xffffffffu, s, o);
                if (!lane) sLoc[wid] = __fdividef(AW, s);
            }
            __syncthreads();
            // column partials -> scalar atomic accumulate; zero next buffer
            {
                int p = git % 3;
                float a0 = 0.f;
                #pragma unroll
                for (int rr = 0; rr < RPB; rr++)
                    a0 += sKs[rr*N_ + tid] * sLoc[rr];
                atomicAdd(&g_csum[p][bb*N_ + tid], a0);
                if (tid < 128) {
                    float a1 = 0.f;
                    #pragma unroll
                    for (int rr = 0; rr < RPB; rr++)
                        a1 += sKs[rr*N_ + tid + 384] * sLoc[rr];
                    atomicAdd(&g_csum[p][bb*N_ + tid + 384], a1);
                }
                int pn = (p + 1 == 3) ? 0 : p + 1;
                if (tid < 8) g_csum[pn][bb*N_ + lid6*8 + tid] = 0.f;
            }
            gsync(gen, ctr);
            // t recompute (redundant per block, into SMEM)
            {
                int p = git % 3;
                tS[tid] = __fdividef(BW, g_csum[p][bb*N_ + tid]);
                if (tid < 128)
                    tS[tid + 384] = __fdividef(BW, g_csum[p][bb*N_ + tid + 384]);
            }
            __syncthreads();
        }

        // P update + row masses (warp per row)
        {
            float s = 0.f;
            for (int q = lane; q < 128; q += 32) {
                float4 v  = *(const float4*)&sKs[wid*N_ + q*4];
                float4 t4 = *(const float4*)&tS[q*4];
                s += v.x*t4.x + v.y*t4.y + v.z*t4.z + v.w*t4.w;
            }
            #pragma unroll
            for (int o = 16; o; o >>= 1) s += __shfl_xor_sync(0xffffffffu, s, o);
            if (!lane) g_rm[bid*RPB + wid] = sLoc[wid] * s;
        }
        for (int c = tid; c < RPB*N_; c += NTHR) {
            int rr = c >> 9, j = c & 511;
            g_P[rowbase + c] = sLoc[rr] * sKs[c] * tS[j];
        }
        gsync(gen, ctr);
    }

    // ---------- Final cost ----------
    gemm_tile<0>(bid, D1, D2, As, Bs, sRed);
    sqmv_t1(D1, bid, wid, lane);
    gsync(gen, ctr);

    gemm_tile<2>(bid, D1, D2, As, Bs, sRed);
    __syncthreads();
    if (lid6 == 0) {                       // blocks 0, 64: rm . t1
        float s = 0.f;
        for (int i = tid; i < M_; i += NTHR) s += g_rm[bb*M_ + i] * g_t1[bb*M_ + i];
        sRed[tid] = s;
        __syncthreads();
        if (tid < 128) sRed[tid] += sRed[tid + 128] + sRed[tid + 256];
        __syncthreads();
        for (int st = 64; st; st >>= 1) {
            if (tid < st) sRed[tid] += sRed[tid + st];
            __syncthreads();
        }
        if (!tid) g_acc[bb] = sRed[0];
    } else if (lid6 == 1) {                // blocks 1, 65: BW * sum t2
        float s = 0.f;
        for (int j = tid; j < N_; j += NTHR) s += g_t2[bb*N_ + j];
        sRed[tid] = s;
        __syncthreads();
        if (tid < 128) sRed[tid] += sRed[tid + 128] + sRed[tid + 256];
        __syncthreads();
        for (int st = 64; st; st >>= 1) {
            if (tid < st) sRed[tid] += sRed[tid + st];
            __syncthreads();
        }
        if (!tid) g_acc[2 + bb] = BW * sRed[0];
    }
    gsync(gen, ctr);

    // outputs
    if (lid6 == 0 && tid == 0) {
        float cr = 0.f;
        for (int t = 0; t < 64; t++) cr += g_cp[bb*64 + t];
        out[bb] = g_acc[bb] + g_acc[2 + bb] - 2.0f*cr;
    }
    if (out_size > 2) {
        const float2* src = (const float2*)(g_P + rowbase);
        float2* dst = (float2*)(out + 2 + rowbase);
        for (int idx = tid; idx < RPB*N_/2; idx += NTHR) dst[idx] = src[idx];
    }
}

// ---------------- host driver ----------------
extern "C" void kernel_launch(void* const* d_in, const int* in_sizes, int n_in,
                              void* d_out, int out_size) {
    const float* D1 = (const float*)d_in[0];
    const float* D2 = (const float*)d_in[1];
    if (n_in >= 2 && in_sizes[0] == B_*N_*N_ && in_sizes[1] == B_*M_*M_) {
        const float* tmp = D1; D1 = D2; D2 = tmp;
    }
    float* out = (float*)d_out;

    static int configured = 0;
    if (!configured) {
        cudaFuncSetAttribute(gw_kernel,
                             cudaFuncAttributeMaxDynamicSharedMemorySize,
                             SMEM_BYTES);
        configured = 1;
    }
    reset_kernel<<<1, 1>>>();
    gw_kernel<<<NBLK, NTHR, SMEM_BYTES>>>(D1, D2, out, out_size);
}

// round 17
// speedup vs baseline: 1.5076x; 1.0064x over previous
#include <cuda_runtime.h>

#define NBLK 128
#define NTHR 384
#define B_ 2
#define M_ 768
#define N_ 512
#define MN_ (M_*N_)
#define AW (1.0f/768.0f)
#define BW (1.0f/512.0f)
#define EPSI 20.0f
#define RPB 12            // rows per block: 128*12 = 1536 = B*M
#define AS_STRIDE 100     // 96+4: multiple of 4 floats -> aligned broadcast LDS.128
#define AS_BUF (16*AS_STRIDE)
#define BS_BUF (16*64)

// dynamic smem layout (floats)
#define OFF_KS   0                       // 12*512 = 6144
#define OFF_AS   6144                    // 2*1600 = 3200
#define OFF_BS   (OFF_AS + 2*AS_BUF)     // 2*1024 = 2048
#define OFF_TS   (OFF_BS + 2*BS_BUF)     // 512
#define OFF_RED  (OFF_TS + 512)          // 384
#define OFF_LOC  (OFF_RED + NTHR)        // 16
#define SMEM_FLOATS (OFF_LOC + 16)
#define SMEM_BYTES  (SMEM_FLOATS*4)

typedef unsigned long long ull;

// ---------------- device scratch ----------------
__device__ float g_P [B_*MN_];
__device__ float g_Km[B_*MN_];
__device__ float g_T [B_*MN_];
__device__ float g_rm[B_*M_];
__device__ float g_t1[B_*M_];
__device__ float g_t2[B_*N_];
__device__ float g_csum[3][B_*N_];   // triple-buffered atomic column sums
__device__ float g_cp[128];
__device__ float g_acc[4];
__device__ unsigned g_bar[64];       // [0] batch0 counter, [32] batch1

__global__ void reset_kernel() { g_bar[0] = 0u; g_bar[32] = 0u; }

// ------- per-batch count barrier (R5/R10): release-arrive, acquire-poll ----
__device__ __forceinline__ void gsync(unsigned &gen, unsigned* ctr) {
    ++gen;
    __syncthreads();
    if (threadIdx.x == 0) {
        asm volatile("red.release.gpu.global.add.u32 [%0], %1;"
                     :: "l"(ctr), "r"(1u) : "memory");
        unsigned target = gen * 64u;
        unsigned v;
        do {
            asm volatile("ld.acquire.gpu.global.b32 %0, [%1];"
                         : "=r"(v) : "l"(ctr) : "memory");
        } while (v < target);
    }
    __syncthreads();
}

// ---------------- packed f32x2 helpers ----------------
__device__ __forceinline__ void fma2(ull &d, ull a, ull b) {
    asm("fma.rn.f32x2 %0, %1, %2, %0;" : "+l"(d) : "l"(a), "l"(b));
}
__device__ __forceinline__ ull splat(float x) {
    ull r; asm("mov.b64 %0, {%1, %1};" : "=l"(r) : "f"(x)); return r;
}

// ---------------- GEMM tile 96x64 (128 tiles), 384 thr, micro 8x2 ----------
// Warp = row-group of 8 rows (A reads single-address broadcast LDS.128),
// lane = column pair (B reads conflict-free LDS.64).
template<int MODE>
__device__ void gemm_tile(int tile, const float* __restrict__ D1,
                          const float* __restrict__ D2,
                          float* As, float* Bs, float* red) {
    const int Kd  = (MODE == 0) ? N_ : M_;
    const int lda = (MODE == 0) ? N_ : M_;
    int b = tile >> 6;
    int r = tile & 63;
    int row0 = (r >> 3) * 96;
    int col0 = (r & 7) * 64;
    const float* A  = (MODE == 0) ? (g_P + (size_t)b*MN_) : (D1 + (size_t)b*M_*M_);
    const float* Bm = (MODE == 0) ? (D2 + (size_t)b*(size_t)N_*N_)
                    : (MODE == 1) ? (g_T + (size_t)b*MN_)
                                  : (g_P + (size_t)b*MN_);
    int tid = threadIdx.x;
    int wid8 = (tid >> 5) * 8;
    int lane = tid & 31;
    int colp = lane * 2;

    int lr = tid >> 2;
    int lk = (tid & 3) * 4;
    const float* ApL = A + (size_t)(row0 + lr)*lda + lk;
    int brow = tid >> 4, bq = tid & 15;
    const float* BpL = Bm + (size_t)brow*N_ + col0 + bq*4;

    ull acc[4][2];
    #pragma unroll
    for (int i = 0; i < 4; i++) { acc[i][0] = 0ull; acc[i][1] = 0ull; }

    float4 pa = *(const float4*)(ApL);
    float4 pb;
    if (tid < 256) pb = *(const float4*)(BpL);

    int buf = 0;
    for (int k0 = 0; k0 < Kd; k0 += 16) {
        float* Asb = As + buf*AS_BUF;
        float* Bsb = Bs + buf*BS_BUF;
        Asb[(lk+0)*AS_STRIDE + lr] = pa.x;
        Asb[(lk+1)*AS_STRIDE + lr] = pa.y;
        Asb[(lk+2)*AS_STRIDE + lr] = pa.z;
        Asb[(lk+3)*AS_STRIDE + lr] = pa.w;
        if (tid < 256) *(float4*)&Bsb[brow*64 + bq*4] = pb;
        if (k0 + 16 < Kd) {
            pa = *(const float4*)(ApL + k0 + 16);
            if (tid < 256) pb = *(const float4*)(BpL + (size_t)(k0+16)*N_);
        }
        __syncthreads();
        #pragma unroll
        for (int k = 0; k < 16; k++) {
            const float* ap = Asb + k*AS_STRIDE + wid8;
            ulonglong2 ua0 = *(const ulonglong2*)(ap);      // rows 0-3 (broadcast)
            ulonglong2 ua1 = *(const ulonglong2*)(ap + 4);  // rows 4-7 (broadcast)
            float2 bv = *(const float2*)&Bsb[k*64 + colp];
            ull b0 = splat(bv.x), b1 = splat(bv.y);
            fma2(acc[0][0], ua0.x, b0); fma2(acc[0][1], ua0.x, b1);
            fma2(acc[1][0], ua0.y, b0); fma2(acc[1][1], ua0.y, b1);
            fma2(acc[2][0], ua1.x, b0); fma2(acc[2][1], ua1.x, b1);
            fma2(acc[3][0], ua1.y, b0); fma2(acc[3][1], ua1.y, b1);
        }
        buf ^= 1;
    }

    float cS[8][2];
    #pragma unroll
    for (int p = 0; p < 4; p++)
        #pragma unroll
        for (int j = 0; j < 2; j++) {
            union { ull u; float f[2]; } cv; cv.u = acc[p][j];
            cS[2*p][j]   = cv.f[0];
            cS[2*p+1][j] = cv.f[1];
        }

    if (MODE == 0) {
        float* Cb = g_T + (size_t)b*MN_;
        #pragma unroll
        for (int rr = 0; rr < 8; rr++) {
            int row = row0 + wid8 + rr;
            float2 v = make_float2(cS[rr][0], cS[rr][1]);
            *(float2*)(Cb + (size_t)row*N_ + col0 + colp) = v;
        }
    } else if (MODE == 1) {
        float* Cb = g_Km + (size_t)b*MN_;
        const float* t1b = g_t1 + b*M_;
        const float* t2b = g_t2 + b*N_;
        float t20 = t2b[col0+colp], t21 = t2b[col0+colp+1];
        #pragma unroll
        for (int rr = 0; rr < 8; rr++) {
            int row = row0 + wid8 + rr;
            float t1v = t1b[row];
            float2 v;
            v.x = __expf((2.0f*cS[rr][0] - t1v - t20) * EPSI);
            v.y = __expf((2.0f*cS[rr][1] - t1v - t21) * EPSI);
            *(float2*)(Cb + (size_t)row*N_ + col0 + colp) = v;
        }
    } else {
        const float* Tb = g_T + (size_t)b*MN_;
        float local = 0.f;
        #pragma unroll
        for (int rr = 0; rr < 8; rr++) {
            int row = row0 + wid8 + rr;
            float2 tv = *(const float2*)(Tb + (size_t)row*N_ + col0 + colp);
            local += cS[rr][0]*tv.x + cS[rr][1]*tv.y;
        }
        red[tid] = local;
        __syncthreads();
        if (tid < 128) red[tid] += red[tid + 128] + red[tid + 256];
        __syncthreads();
        for (int st = 64; st; st >>= 1) {
            if (tid < st) red[tid] += red[tid + st];
            __syncthreads();
        }
        if (!tid) g_cp[tile] = red[0];
    }
}

// ---------------- t1 = (D1.^2) @ rm  (warp per row, 12 warps) --------------
__device__ void sqmv_t1(const float* __restrict__ D1, int bid, int wid, int lane) {
    int fi = bid*RPB + wid;
    int b2 = fi >= M_;
    int i  = fi - b2*M_;
    const float4* row = (const float4*)(D1 + ((size_t)b2*M_ + i)*M_);
    const float4* rmb = (const float4*)(g_rm + b2*M_);
    float s = 0.f;
    for (int q = lane; q < 192; q += 32) {
        float4 v  = row[q];
        float4 r4 = rmb[q];
        s += v.x*v.x*r4.x + v.y*v.y*r4.y + v.z*v.z*r4.z + v.w*v.w*r4.w;
    }
    #pragma unroll
    for (int o = 16; o; o >>= 1) s += __shfl_xor_sync(0xffffffffu, s, o);
    if (!lane) g_t1[fi] = s;
}

// ---------------- persistent mega-kernel ----------------
__global__ void __launch_bounds__(NTHR)
gw_kernel(const float* __restrict__ D1, const float* __restrict__ D2,
          float* __restrict__ out, int out_size) {
    extern __shared__ float dyn[];
    float* sKs  = dyn + OFF_KS;
    float* As   = dyn + OFF_AS;
    float* Bs   = dyn + OFF_BS;
    float* tS   = dyn + OFF_TS;
    float* sRed = dyn + OFF_RED;
    float* sLoc = dyn + OFF_LOC;

    int bid = blockIdx.x, tid = threadIdx.x;
    int wid = tid >> 5, lane = tid & 31;
    unsigned gen = 0;
    int bb = bid >> 6;                          // batch (64 blocks each)
    int lid6 = bid & 63;
    unsigned* ctr = &g_bar[bb*32];
    size_t rowbase = (size_t)bid * (RPB*N_);

    // ---------- Phase I: init P, rm, t2, csum[0] ----------
    for (int idx = tid; idx < RPB*N_; idx += NTHR) g_P[rowbase + idx] = AW*BW;
    if (tid < RPB) g_rm[bid*RPB + tid] = AW;
    if (wid < 8) {
        int gw2 = bid*8 + wid;
        int b2 = gw2 >> 9, j = gw2 & 511;
        const float4* row = (const float4*)(D2 + ((size_t)b2*N_ + j)*N_);
        float s = 0.f;
        for (int q = lane; q < 128; q += 32) {
            float4 v = row[q];
            s += v.x*v.x + v.y*v.y + v.z*v.z + v.w*v.w;
        }
        #pragma unroll
        for (int o = 16; o; o >>= 1) s += __shfl_xor_sync(0xffffffffu, s, o);
        if (!lane) g_t2[gw2] = BW * s;
    }
    if (lid6 == 0)
        for (int idx = tid; idx < N_; idx += NTHR) g_csum[0][bb*N_ + idx] = 0.f;
    gsync(gen, ctr);

    int git = 0;
    for (int outer = 0; outer < 10; outer++) {
        // Phase A: T = P@D2 (1 tile/block) + t1 sqmv
        gemm_tile<0>(bid, D1, D2, As, Bs, sRed);
        sqmv_t1(D1, bid, wid, lane);
        gsync(gen, ctr);

        // Phase B: Km = exp(...)
        gemm_tile<1>(bid, D1, D2, As, Bs, sRed);
        gsync(gen, ctr);

        // Sinkhorn: 20 iterations, 1 barrier each
        for (int it = 0; it < 20; it++, git++) {
            if (it == 0) {
                const float4* src = (const float4*)(g_Km + rowbase);
                float4* dst = (float4*)sKs;
                for (int idx = tid; idx < RPB*N_/4; idx += NTHR) dst[idx] = src[idx];
                __syncthreads();
            }
            // u-dot: warp wid handles row wid
            {
                float s = 0.f;
                if (it == 0) {
                    for (int q = lane; q < 128; q += 32) {
                        float4 v = *(const float4*)&sKs[wid*N_ + q*4];
                        s += v.x + v.y + v.z + v.w;
                    }
                } else {
                    for (int q = lane; q < 128; q += 32) {
                        float4 v  = *(const float4*)&sKs[wid*N_ + q*4];
                        float4 t4 = *(const float4*)&tS[q*4];
                        s += v.x*t4.x + v.y*t4.y + v.z*t4.z + v.w*t4.w;
                    }
                }
                #pragma unroll
                for (int o = 16; o; o >>= 1) s += __shfl_xor_sync(0xffffffffu, s, o);
                if (!lane) sLoc[wid] = __fdividef(AW, s);
            }
            __syncthreads();
            // column partials -> scalar atomic accumulate;
            // next-buffer zeroing done by non-dual-RED threads (376..383)
            {
                int p = git % 3;
                float a0 = 0.f;
                #pragma unroll
                for (int rr = 0; rr < RPB; rr++)
                    a0 += sKs[rr*N_ + tid] * sLoc[rr];
                atomicAdd(&g_csum[p][bb*N_ + tid], a0);
                if (tid < 128) {
                    float a1 = 0.f;
                    #pragma unroll
                    for (int rr = 0; rr < RPB; rr++)
                        a1 += sKs[rr*N_ + tid + 384] * sLoc[rr];
                    atomicAdd(&g_csum[p][bb*N_ + tid + 384], a1);
                }
                int pn = (p + 1 == 3) ? 0 : p + 1;
                if (tid >= 376) g_csum[pn][bb*N_ + lid6*8 + (tid - 376)] = 0.f;
            }
            gsync(gen, ctr);
            // t recompute: vectorized (128 threads x LDG.128 + 4 div + STS.128)
            {
                int p = git % 3;
                if (tid < 128) {
                    float4 c = *(const float4*)&g_csum[p][bb*N_ + tid*4];
                    float4 t4;
                    t4.x = __fdividef(BW, c.x);
                    t4.y = __fdividef(BW, c.y);
                    t4.z = __fdividef(BW, c.z);
                    t4.w = __fdividef(BW, c.w);
                    *(float4*)&tS[tid*4] = t4;
                }
            }
            __syncthreads();
        }

        // P update + row masses (warp per row)
        {
            float s = 0.f;
            for (int q = lane; q < 128; q += 32) {
                float4 v  = *(const float4*)&sKs[wid*N_ + q*4];
                float4 t4 = *(const float4*)&tS[q*4];
                s += v.x*t4.x + v.y*t4.y + v.z*t4.z + v.w*t4.w;
            }
            #pragma unroll
            for (int o = 16; o; o >>= 1) s += __shfl_xor_sync(0xffffffffu, s, o);
            if (!lane) g_rm[bid*RPB + wid] = sLoc[wid] * s;
        }
        for (int c = tid; c < RPB*N_; c += NTHR) {
            int rr = c >> 9, j = c & 511;
            g_P[rowbase + c] = sLoc[rr] * sKs[c] * tS[j];
        }
        gsync(gen, ctr);
    }

    // ---------- Final cost ----------
    gemm_tile<0>(bid, D1, D2, As, Bs, sRed);
    sqmv_t1(D1, bid, wid, lane);
    gsync(gen, ctr);

    gemm_tile<2>(bid, D1, D2, As, Bs, sRed);
    __syncthreads();
    if (lid6 == 0) {                       // blocks 0, 64: rm . t1
        float s = 0.f;
        for (int i = tid; i < M_; i += NTHR) s += g_rm[bb*M_ + i] * g_t1[bb*M_ + i];
        sRed[tid] = s;
        __syncthreads();
        if (tid < 128) sRed[tid] += sRed[tid + 128] + sRed[tid + 256];
        __syncthreads();
        for (int st = 64; st; st >>= 1) {
            if (tid < st) sRed[tid] += sRed[tid + st];
            __syncthreads();
        }
        if (!tid) g_acc[bb] = sRed[0];
    } else if (lid6 == 1) {                // blocks 1, 65: BW * sum t2
        float s = 0.f;
        for (int j = tid; j < N_; j += NTHR) s += g_t2[bb*N_ + j];
        sRed[tid] = s;
        __syncthreads();
        if (tid < 128) sRed[tid] += sRed[tid + 128] + sRed[tid + 256];
        __syncthreads();
        for (int st = 64; st; st >>= 1) {
            if (tid < st) sRed[tid] += sRed[tid + st];
            __syncthreads();
        }
        if (!tid) g_acc[2 + bb] = BW * sRed[0];
    }
    gsync(gen, ctr);

    // outputs
    if (lid6 == 0 && tid == 0) {
        float cr = 0.f;
        for (int t = 0; t < 64; t++) cr += g_cp[bb*64 + t];
        out[bb] = g_acc[bb] + g_acc[2 + bb] - 2.0f*cr;
    }
    if (out_size > 2) {
        const float2* src = (const float2*)(g_P + rowbase);
        float2* dst = (float2*)(out + 2 + rowbase);
        for (int idx = tid; idx < RPB*N_/2; idx += NTHR) dst[idx] = src[idx];
    }
}

// ---------------- host driver ----------------
extern "C" void kernel_launch(void* const* d_in, const int* in_sizes, int n_in,
                              void* d_out, int out_size) {
    const float* D1 = (const float*)d_in[0];
    const float* D2 = (const float*)d_in[1];
    if (n_in >= 2 && in_sizes[0] == B_*N_*N_ && in_sizes[1] == B_*M_*M_) {
        const float* tmp = D1; D1 = D2; D2 = tmp;
    }
    float* out = (float*)d_out;

    static int configured = 0;
    if (!configured) {
        cudaFuncSetAttribute(gw_kernel,
                             cudaFuncAttributeMaxDynamicSharedMemorySize,
                             SMEM_BYTES);
        configured = 1;
    }
    reset_kernel<<<1, 1>>>();
    gw_kernel<<<NBLK, NTHR, SMEM_BYTES>>>(D1, D2, out, out_size);
}